// round 13
// baseline (speedup 1.0000x reference)
#include <cuda_runtime.h>

#define SPATIAL  3136
#define NBW      128
#define SCALE2   0.35355339059327373f   // 2/sqrt(32)

// phase1: one 4-row chunk per block; 112 positions = 28 16B-lines per channel
#define C1_ROWB   512                   // 32 slots * 16B (28 used + swizzle room)
#define C1_TEN    16384                 // 32 channels * 512B
#define C1_SMEM   32768                 // K + V

#define NCH       14                    // 4-row chunks per window

__device__ float g_Pp[NBW * NCH * 1024];   // partial K^T V per (bw, chunk)

typedef unsigned long long ull;

__device__ __forceinline__ void fma2(ull& d, ull a, ull b) {
    asm("fma.rn.f32x2 %0, %1, %2, %0;" : "+l"(d) : "l"(a), "l"(b));
}
__device__ __forceinline__ ull rep2(float x) {
    ull r; asm("mov.b64 %0, {%1, %1};" : "=l"(r) : "f"(x)); return r;
}
__device__ __forceinline__ float lo32(ull x) { return __uint_as_float((unsigned)x); }
__device__ __forceinline__ float hi32(ull x) { return __uint_as_float((unsigned)(x >> 32)); }
__device__ __forceinline__ void cp16(unsigned dst, const void* src) {
    asm volatile("cp.async.cg.shared.global [%0], [%1], 16;" :: "r"(dst), "l"(src));
}

// ---------------------------------------------------------------------------
// Phase 1: partial P = K_chunk^T V_chunk. grid (128 bw, 14 chunks), 128 thr.
// Small quantum (32KB KV tile), 5 blocks/SM. Tile 8c1 x 4c2 per thread.
// ---------------------------------------------------------------------------
__global__ __launch_bounds__(128, 5)
void phase1(const float* __restrict__ K, const float* __restrict__ V) {
    extern __shared__ __align__(16) char sm[];
    const unsigned sm32 = (unsigned)__cvta_generic_to_shared(sm);

    const int tid = threadIdx.x;
    const int bw  = blockIdx.x;
    const int ck  = blockIdx.y;                    // 0..13
    const int win  = bw & 1;
    const int head = (bw >> 1) & 7;
    const int tb   = bw >> 4;
    const int gch  = (tb * 256 + head * 32) * SPATIAL + win * 28 + ck * 224;

    // stage K+V chunk: 2 tensors * 32ch * 28 lines = 1792 lines, 14/thread
    #pragma unroll
    for (int it = 0; it < 14; it++) {
        int idx = it * 128 + tid;                  // 0..1791
        int tensor = (idx >= 896) ? 1 : 0;
        int rem = idx - tensor * 896;              // 0..895
        int c = rem / 28;
        int g = rem - c * 28;                      // line 0..27
        int r = g / 7;
        int w4 = g - r * 7;
        const float* src = (tensor ? V : K) + gch + c * SPATIAL + r * 56 + w4 * 4;
        int slot = g ^ ((c >> 2) & 7);
        cp16(sm32 + tensor * C1_TEN + c * C1_ROWB + slot * 16, src);
    }
    asm volatile("cp.async.commit_group;");

    const int w    = tid >> 5;                     // warp: 7 lines each
    const int lane = tid & 31;
    const int ti   = lane & 3;                     // 8 c1 channels
    const int tj   = lane >> 2;                    // 4 c2 channels
    const int keyA = ti * 2;
    const int keyB = ti * 2 + 1;

    ull acc[8][4];
    #pragma unroll
    for (int i = 0; i < 8; i++)
        #pragma unroll
        for (int j = 0; j < 4; j++) acc[i][j] = 0ull;

    asm volatile("cp.async.wait_group 0;");
    __syncthreads();

    const char* kB = sm;
    const char* vB = sm + C1_TEN;

    #pragma unroll
    for (int u = 0; u < 7; u++) {
        const int line = w * 7 + u;                // 0..27
        ulonglong2 vv[4];
        #pragma unroll
        for (int j = 0; j < 4; j++)
            vv[j] = *(const ulonglong2*)(vB + (tj * 4 + j) * C1_ROWB
                      + ((line ^ tj) << 4));
        {
            ulonglong2 kk[4];
            #pragma unroll
            for (int i2 = 0; i2 < 4; i2++)
                kk[i2] = *(const ulonglong2*)(kB + (ti * 8 + i2) * C1_ROWB
                          + ((line ^ keyA) << 4));
            #pragma unroll
            for (int i2 = 0; i2 < 4; i2++)
                #pragma unroll
                for (int j = 0; j < 4; j++) {
                    fma2(acc[i2][j], kk[i2].x, vv[j].x);
                    fma2(acc[i2][j], kk[i2].y, vv[j].y);
                }
        }
        {
            ulonglong2 kk[4];
            #pragma unroll
            for (int i2 = 0; i2 < 4; i2++)
                kk[i2] = *(const ulonglong2*)(kB + (ti * 8 + 4 + i2) * C1_ROWB
                          + ((line ^ keyB) << 4));
            #pragma unroll
            for (int i2 = 0; i2 < 4; i2++)
                #pragma unroll
                for (int j = 0; j < 4; j++) {
                    fma2(acc[4 + i2][j], kk[i2].x, vv[j].x);
                    fma2(acc[4 + i2][j], kk[i2].y, vv[j].y);
                }
        }
    }
    __syncthreads();                               // KV reads done; reuse smem

    // reduce 4 warps via smem
    float* red = (float*)sm;                       // 4 * 1024 floats = 16KB
    #pragma unroll
    for (int i2 = 0; i2 < 8; i2++)
        #pragma unroll
        for (int j = 0; j < 4; j++)
            red[w * 1024 + (ti * 8 + i2) * 32 + tj * 4 + j] =
                lo32(acc[i2][j]) + hi32(acc[i2][j]);
    __syncthreads();

    float* gp = g_Pp + (bw * NCH + ck) * 1024;
    #pragma unroll
    for (int t = 0; t < 8; t++) {
        const int o = tid + t * 128;
        gp[o] = red[o] + red[1024 + o] + red[2048 + o] + red[3072 + o];
    }
}

// ---------------------------------------------------------------------------
// Phase 2 (R12): out = Q * P. grid (128 bw, 14 chunks of 4 rows), 128 thr.
// Sums the 14 partials (L2-hot) into ps while Q stages.
// ---------------------------------------------------------------------------
__global__ __launch_bounds__(128, 6)
void phase2(const float* __restrict__ Q, float* __restrict__ O) {
    __shared__ __align__(16) float qs[32 * 112];
    __shared__ __align__(16) float ps[1024];

    const int tid = threadIdx.x;
    const int bw  = blockIdx.x;
    const int ck  = blockIdx.y;                    // 0..13
    const int win  = bw & 1;
    const int head = (bw >> 1) & 7;
    const int tb   = bw >> 4;
    const int base = (tb * 256 + head * 32) * SPATIAL + win * 28 + ck * 224;

    // stage Q tile via cp.async: 896 lines / 128 thr = 7 each
    const unsigned qsa = (unsigned)__cvta_generic_to_shared(qs);
    #pragma unroll
    for (int it = 0; it < 7; it++) {
        int idx = it * 128 + tid;                  // 0..895
        int c = idx / 28;
        int g = idx - c * 28;
        int r = g / 7;
        int w4 = g - r * 7;
        cp16(qsa + (c * 112 + g * 4) * 4,
             Q + base + c * SPATIAL + r * 56 + w4 * 4);
    }
    asm volatile("cp.async.commit_group;");

    // ps = scale * sum of 14 partials while Q streams
    {
        const float* p0 = g_Pp + bw * (NCH * 1024);
        #pragma unroll
        for (int t = 0; t < 2; t++) {
            const int i4 = (tid + t * 128) * 4;
            float4 s = make_float4(0.f, 0.f, 0.f, 0.f);
            #pragma unroll
            for (int c = 0; c < NCH; c++) {
                float4 a = *(const float4*)(p0 + c * 1024 + i4);
                s.x += a.x; s.y += a.y; s.z += a.z; s.w += a.w;
            }
            s.x *= SCALE2; s.y *= SCALE2; s.z *= SCALE2; s.w *= SCALE2;
            *(float4*)&ps[i4] = s;
        }
    }

    asm volatile("cp.async.wait_group 0;");
    __syncthreads();

    const int c2g  = tid & 3;                      // 8 c2 each
    const int posg = tid >> 2;                     // 0..31, active < 28
    if (posg >= 28) return;
    const int pbase = posg * 4;

    ull a[2][8];
    #pragma unroll
    for (int p = 0; p < 2; p++)
        #pragma unroll
        for (int j = 0; j < 8; j++) a[p][j] = 0ull;

    #pragma unroll
    for (int c1 = 0; c1 < 32; c1++) {
        ulonglong2 q2 = *(const ulonglong2*)&qs[c1 * 112 + pbase];
        float4 pa = *(const float4*)&ps[c1 * 32 + c2g * 8];
        float4 pb = *(const float4*)&ps[c1 * 32 + c2g * 8 + 4];
        const float pv[8] = {pa.x, pa.y, pa.z, pa.w, pb.x, pb.y, pb.z, pb.w};
        #pragma unroll
        for (int j = 0; j < 8; j++) {
            ull pj = rep2(pv[j]);
            fma2(a[0][j], q2.x, pj);
            fma2(a[1][j], q2.y, pj);
        }
    }

    const int rr = pbase / 28;
    const int ww = pbase - rr * 28;
    float* ob = O + base + rr * 56 + ww;
    #pragma unroll
    for (int j = 0; j < 8; j++) {
        const int c2 = c2g * 8 + j;
        float4 o4;
        o4.x = lo32(a[0][j]);
        o4.y = hi32(a[0][j]);
        o4.z = lo32(a[1][j]);
        o4.w = hi32(a[1][j]);
        *(float4*)(ob + c2 * SPATIAL) = o4;
    }
}

// ---------------------------------------------------------------------------
extern "C" void kernel_launch(void* const* d_in, const int* in_sizes, int n_in,
                              void* d_out, int out_size) {
    const float* q = (const float*)d_in[0];
    const float* k = (const float*)d_in[1];
    const float* v = (const float*)d_in[2];
    float* out = (float*)d_out;

    cudaFuncSetAttribute(phase1, cudaFuncAttributeMaxDynamicSharedMemorySize, C1_SMEM);

    phase1<<<dim3(NBW, NCH), 128, C1_SMEM>>>(k, v);
    phase2<<<dim3(NBW, NCH), 128>>>(q, out);
}

// round 14
// speedup vs baseline: 1.2302x; 1.2302x over previous
#include <cuda_runtime.h>

#define SPATIAL  3136
#define NBW      128
#define SCALE2   0.35355339059327373f   // 2/sqrt(32)

// phase1: 4-row chunks = 112 positions = 56 pairs, 28 16B-lines per channel
#define P1_ROWB   512
#define P1_TEN    (32 * P1_ROWB)
#define P1_BUF    (2 * P1_TEN)
#define P1_SMEM   (3 * P1_BUF)          // 98304
#define P1_LPT    896

// phase2: tf32 mma tiles
#define QPITCH    72                    // floats; banks 8k+r conflict-free
#define PPITCH    40                    // floats; 32 distinct banks

__device__ float g_Pp[NBW * 2 * 1024];

typedef unsigned long long ull;

__device__ __forceinline__ void fma2(ull& d, ull a, ull b) {
    asm("fma.rn.f32x2 %0, %1, %2, %0;" : "+l"(d) : "l"(a), "l"(b));
}
__device__ __forceinline__ float lo32(ull x) { return __uint_as_float((unsigned)x); }
__device__ __forceinline__ float hi32(ull x) { return __uint_as_float((unsigned)(x >> 32)); }
__device__ __forceinline__ void cp16(unsigned dst, const void* src) {
    asm volatile("cp.async.cg.shared.global [%0], [%1], 16;" :: "r"(dst), "l"(src));
}
__device__ __forceinline__ unsigned f2tf(float x) {
    unsigned r; asm("cvt.rna.tf32.f32 %0, %1;" : "=r"(r) : "f"(x)); return r;
}

// ---------------------------------------------------------------------------
// Phase 1 (R5 verbatim): partial P = K^T V. grid (128,2), 256 thr, 2 blk/SM.
// ---------------------------------------------------------------------------
__global__ __launch_bounds__(256, 2)
void phase1(const float* __restrict__ K, const float* __restrict__ V) {
    extern __shared__ __align__(16) char sm[];
    const unsigned sm32 = (unsigned)__cvta_generic_to_shared(sm);

    const int tid  = threadIdx.x;
    const int bw   = blockIdx.x;
    const int sl   = blockIdx.y;
    const int c0   = sl * 7;

    const int win  = bw & 1;
    const int head = (bw >> 1) & 7;
    const int tb   = bw >> 4;
    const int base = (tb * 256 + head * 32) * SPATIAL + win * 28;

    const int ti  = tid & 3;
    const int tj  = (tid >> 2) & 7;
    const int wid = tid >> 5;
    const int keyA = ti * 2;
    const int keyB = ti * 2 + 1;

    auto stage = [&](int ch, int buf) {
        const unsigned bufb = sm32 + buf * P1_BUF;
        const int gofs = base + ch * 224;
        #pragma unroll
        for (int it = 0; it < 7; it++) {
            int idx = it * 256 + tid;
            int tensor = (idx >= P1_LPT) ? 1 : 0;
            int rem = idx - tensor * P1_LPT;
            int c = rem / 28;
            int g = rem - c * 28;
            int r = g / 7;
            int w4 = g - r * 7;
            const float* src = (tensor ? V : K) + gofs + c * SPATIAL + r * 56 + w4 * 4;
            int chs = g ^ ((c >> 2) & 7);
            cp16(bufb + tensor * P1_TEN + c * P1_ROWB + chs * 16, src);
        }
        asm volatile("cp.async.commit_group;");
    };

    ull acc[8][4];
    #pragma unroll
    for (int i = 0; i < 8; i++)
        #pragma unroll
        for (int j = 0; j < 4; j++) acc[i][j] = 0ull;

    stage(c0, 0);
    stage(c0 + 1, 1);

    #pragma unroll
    for (int i = 0; i < 7; i++) {
        if (i < 5) {
            stage(c0 + i + 2, (i + 2) % 3);
            asm volatile("cp.async.wait_group 2;");
        } else if (i == 5) {
            asm volatile("cp.async.wait_group 1;");
        } else {
            asm volatile("cp.async.wait_group 0;");
        }
        __syncthreads();

        const char* kB = sm + (i % 3) * P1_BUF;
        const char* vB = kB + P1_TEN;

        auto loadA = [&](int u, ull* ka) {
            const int pr = wid + u * 8;
            const int col = pr >> 1;
            const unsigned off = ((unsigned)(col ^ keyA) << 4) + ((pr & 1) << 3);
            #pragma unroll
            for (int i2 = 0; i2 < 4; i2++)
                ka[i2] = *(const ull*)(kB + (ti * 8 + i2) * P1_ROWB + off);
        };
        auto loadB = [&](int u, ull* kb) {
            const int pr = wid + u * 8;
            const int col = pr >> 1;
            const unsigned off = ((unsigned)(col ^ keyB) << 4) + ((pr & 1) << 3);
            #pragma unroll
            for (int i2 = 0; i2 < 4; i2++)
                kb[i2] = *(const ull*)(kB + (ti * 8 + 4 + i2) * P1_ROWB + off);
        };
        auto loadV = [&](int u, ull* v) {
            const int pr = wid + u * 8;
            const int col = pr >> 1;
            const unsigned off = ((unsigned)(col ^ tj) << 4) + ((pr & 1) << 3);
            #pragma unroll
            for (int j = 0; j < 4; j++)
                v[j] = *(const ull*)(vB + (tj * 4 + j) * P1_ROWB + off);
        };

        ull kkA[4], kkB[4], vv[4], kkA2[4], vv2[4];
        loadA(0, kkA);
        loadV(0, vv);
        #pragma unroll
        for (int u = 0; u < 7; u++) {
            loadB(u, kkB);
            if (u < 6) { loadA(u + 1, kkA2); loadV(u + 1, vv2); }
            #pragma unroll
            for (int i2 = 0; i2 < 4; i2++)
                #pragma unroll
                for (int j = 0; j < 4; j++)
                    fma2(acc[i2][j], kkA[i2], vv[j]);
            #pragma unroll
            for (int i2 = 0; i2 < 4; i2++)
                #pragma unroll
                for (int j = 0; j < 4; j++)
                    fma2(acc[4 + i2][j], kkB[i2], vv[j]);
            if (u < 6) {
                #pragma unroll
                for (int t = 0; t < 4; t++) { kkA[t] = kkA2[t]; vv[t] = vv2[t]; }
            }
        }
        __syncthreads();
    }

    float* red = (float*)sm;
    #pragma unroll
    for (int i2 = 0; i2 < 8; i2++)
        #pragma unroll
        for (int j = 0; j < 4; j++)
            red[wid * 1024 + (ti * 8 + i2) * 32 + tj * 4 + j] =
                lo32(acc[i2][j]) + hi32(acc[i2][j]);
    __syncthreads();

    float* gp = g_Pp + (bw * 2 + sl) * 1024;
    #pragma unroll
    for (int t = 0; t < 4; t++) {
        const int o = tid + t * 256;
        float s = red[o];
        #pragma unroll
        for (int w = 1; w < 8; w++) s += red[w * 1024 + o];
        gp[o] = s;
    }
}

// ---------------------------------------------------------------------------
// Phase 2 (tf32 tensor cores): out = Q * P.
// grid (128 bw, 25 chunks of 64 pos), 128 thr (4 warps x m16 tiles).
// mma.sync.m16n8k8.row.col.f32.tf32: A = Q[16pos x 8c1], B = P[8c1 x 8c2].
// ---------------------------------------------------------------------------
__global__ __launch_bounds__(128, 8)
void phase2(const float* __restrict__ Q, float* __restrict__ O) {
    __shared__ __align__(16) float    qs[32 * QPITCH];     // [c1][pos], pitch 72
    __shared__ __align__(16) unsigned pstf[32 * PPITCH];   // tf32 P [c1][c2], pitch 40

    const int tid = threadIdx.x;
    const int bw  = blockIdx.x;
    const int j   = blockIdx.y;                 // 0..24
    const int win  = bw & 1;
    const int head = (bw >> 1) & 7;
    const int tb   = bw >> 4;
    const int base = (tb * 256 + head * 32) * SPATIAL + win * 28;
    const int p0   = j * 64;

    // stage Q[c1][p0..p0+63] : 512 16B lines, 4/thread (guard tail)
    const unsigned qsa = (unsigned)__cvta_generic_to_shared(qs);
    #pragma unroll
    for (int it = 0; it < 4; it++) {
        int l  = it * 128 + tid;                // 0..511
        int c1 = l >> 4;
        int lp = l & 15;
        int pos = p0 + lp * 4;
        if (pos < 1568) {
            int ir = pos / 28;
            int ic = pos - ir * 28;
            cp16(qsa + (c1 * QPITCH + lp * 4) * 4,
                 Q + base + c1 * SPATIAL + ir * 56 + ic);
        }
    }
    asm volatile("cp.async.commit_group;");

    // P = (partial0 + partial1) * scale, converted to tf32, pitch 40
    {
        const float* pp = g_Pp + bw * 2048;
        #pragma unroll
        for (int t = 0; t < 2; t++) {
            const int idx4 = (tid + t * 128) * 4;
            const int c1 = idx4 >> 5, c2 = idx4 & 31;
            float4 a = *(const float4*)(pp + idx4);
            float4 b = *(const float4*)(pp + 1024 + idx4);
            uint4 s;
            s.x = f2tf((a.x + b.x) * SCALE2);
            s.y = f2tf((a.y + b.y) * SCALE2);
            s.z = f2tf((a.z + b.z) * SCALE2);
            s.w = f2tf((a.w + b.w) * SCALE2);
            *(uint4*)&pstf[c1 * PPITCH + c2] = s;
        }
    }

    asm volatile("cp.async.wait_group 0;");
    __syncthreads();

    const int wid  = tid >> 5;
    const int lane = tid & 31;
    const int pbase = p0 + wid * 16;
    if (pbase >= 1568) return;

    const int g  = lane >> 2;                   // 0..7
    const int t4 = lane & 3;                    // 0..3
    const int plocal = wid * 16 + g;

    float c[4][4];
    #pragma unroll
    for (int nt = 0; nt < 4; nt++)
        #pragma unroll
        for (int x = 0; x < 4; x++) c[nt][x] = 0.f;

    #pragma unroll
    for (int ks = 0; ks < 4; ks++) {
        const int k0 = ks * 8;
        unsigned a0 = f2tf(qs[(k0 + t4) * QPITCH + plocal]);
        unsigned a1 = f2tf(qs[(k0 + t4) * QPITCH + plocal + 8]);
        unsigned a2 = f2tf(qs[(k0 + t4 + 4) * QPITCH + plocal]);
        unsigned a3 = f2tf(qs[(k0 + t4 + 4) * QPITCH + plocal + 8]);
        #pragma unroll
        for (int nt = 0; nt < 4; nt++) {
            unsigned b0 = pstf[(k0 + t4) * PPITCH + nt * 8 + g];
            unsigned b1 = pstf[(k0 + t4 + 4) * PPITCH + nt * 8 + g];
            asm volatile(
                "mma.sync.aligned.m16n8k8.row.col.f32.tf32.tf32.f32 "
                "{%0,%1,%2,%3}, {%4,%5,%6,%7}, {%8,%9}, {%0,%1,%2,%3};"
                : "+f"(c[nt][0]), "+f"(c[nt][1]), "+f"(c[nt][2]), "+f"(c[nt][3])
                : "r"(a0), "r"(a1), "r"(a2), "r"(a3), "r"(b0), "r"(b1));
        }
    }

    // stores: c0:(pos_lo, n) c1:(pos_lo, n+1) c2:(pos_hi, n) c3:(pos_hi, n+1)
    const int pos_lo = pbase + g;
    const int pos_hi = pos_lo + 8;
    const int irl = pos_lo / 28, icl = pos_lo - irl * 28;
    const int irh = pos_hi / 28, ich = pos_hi - irh * 28;
    const int offl = irl * 56 + icl;
    const int offh = irh * 56 + ich;

    #pragma unroll
    for (int nt = 0; nt < 4; nt++) {
        const int n = nt * 8 + 2 * t4;
        float* o0 = O + base + n * SPATIAL;
        o0[offl]           = c[nt][0];
        o0[SPATIAL + offl] = c[nt][1];
        o0[offh]           = c[nt][2];
        o0[SPATIAL + offh] = c[nt][3];
    }
}

// ---------------------------------------------------------------------------
extern "C" void kernel_launch(void* const* d_in, const int* in_sizes, int n_in,
                              void* d_out, int out_size) {
    const float* q = (const float*)d_in[0];
    const float* k = (const float*)d_in[1];
    const float* v = (const float*)d_in[2];
    float* out = (float*)d_out;

    cudaFuncSetAttribute(phase1, cudaFuncAttributeMaxDynamicSharedMemorySize, P1_SMEM);

    phase1<<<dim3(NBW, 2), 256, P1_SMEM>>>(k, v);
    phase2<<<dim3(NBW, 25), 128>>>(q, out);
}